// round 11
// baseline (speedup 1.0000x reference)
#include <cuda_runtime.h>
#include <cuda_bf16.h>

// Problem constants (match reference_code)
#define NU    30000
#define NENT  70000
#define NN    100000          // NU + NENT
#define NEDGE 1600000
#define NB    4096

#define SCAN_ELEMS 512
#define NBLK_SCAN  ((NN + SCAN_ELEMS - 1) / SCAN_ELEMS)   // 196

// Scratch (device globals: allocation-free rule).
__device__ float g_feats0[NN * 64];
__device__ float g_a1[NN * 64];
__device__ float g_a2[NN * 32];
// bf16 gather mirrors (read-only in the edge loop)
__device__ __nv_bfloat16 g_f0h[NN * 64];
__device__ __nv_bfloat16 g_a1h[NN * 64];
// CSR scratch
__device__ int   g_cnt[NN];
__device__ int   g_rowptr[NN + 1];
__device__ int   g_cursor[NN];
__device__ int   g_bsum[256];
__device__ int   g_boff[256];
__device__ int2  g_ecv[NEDGE];       // x = col, y = float bits of val

// ---------------------------------------------------------------------------
// K0: a0 = concat(user_embed, entity_embed) + bf16 mirror
// ---------------------------------------------------------------------------
__global__ __launch_bounds__(256) void concat_kernel(
    const float* __restrict__ ue, const float* __restrict__ ee)
{
    int idx = blockIdx.x * 256 + threadIdx.x;           // over NN*16 float4
    if (idx >= NN * 16) return;
    float4 v = (idx < NU * 16) ? ((const float4*)ue)[idx]
                               : ((const float4*)ee)[idx - NU * 16];
    ((float4*)g_feats0)[idx] = v;
    __nv_bfloat162 lo = __float22bfloat162_rn(make_float2(v.x, v.y));
    __nv_bfloat162 hi = __float22bfloat162_rn(make_float2(v.z, v.w));
    ((__nv_bfloat162*)g_f0h)[idx * 2 + 0] = lo;
    ((__nv_bfloat162*)g_f0h)[idx * 2 + 1] = hi;
}

// ---------------------------------------------------------------------------
// CSR build: zero counts -> histogram -> 3-phase exclusive scan -> fill
// ---------------------------------------------------------------------------
__global__ __launch_bounds__(256) void zero_cnt_kernel()
{
    int i = blockIdx.x * 256 + threadIdx.x;
    if (i < NN) g_cnt[i] = 0;
}

__global__ __launch_bounds__(256) void hist_kernel(const int* __restrict__ er)
{
    int e = blockIdx.x * 256 + threadIdx.x;
    if (e < NEDGE) atomicAdd(&g_cnt[er[e]], 1);
}

__global__ __launch_bounds__(SCAN_ELEMS) void scan1_kernel()
{
    __shared__ int s[SCAN_ELEMS];
    int i = blockIdx.x * SCAN_ELEMS + threadIdx.x;
    int v = (i < NN) ? g_cnt[i] : 0;
    s[threadIdx.x] = v;
    __syncthreads();
    #pragma unroll
    for (int off = 1; off < SCAN_ELEMS; off <<= 1) {
        int t = (threadIdx.x >= off) ? s[threadIdx.x - off] : 0;
        __syncthreads();
        s[threadIdx.x] += t;
        __syncthreads();
    }
    if (i < NN) g_rowptr[i] = s[threadIdx.x] - v;        // exclusive within block
    if (threadIdx.x == SCAN_ELEMS - 1) g_bsum[blockIdx.x] = s[SCAN_ELEMS - 1];
}

__global__ __launch_bounds__(256) void scan2_kernel()
{
    __shared__ int s[256];
    int v = (threadIdx.x < NBLK_SCAN) ? g_bsum[threadIdx.x] : 0;
    s[threadIdx.x] = v;
    __syncthreads();
    #pragma unroll
    for (int off = 1; off < 256; off <<= 1) {
        int t = (threadIdx.x >= off) ? s[threadIdx.x - off] : 0;
        __syncthreads();
        s[threadIdx.x] += t;
        __syncthreads();
    }
    g_boff[threadIdx.x] = s[threadIdx.x] - v;            // exclusive
}

__global__ __launch_bounds__(256) void scan3_kernel()
{
    int i = blockIdx.x * 256 + threadIdx.x;
    if (i < NN) {
        int rp = g_rowptr[i] + g_boff[i / SCAN_ELEMS];
        g_rowptr[i] = rp;
        g_cursor[i] = rp;
    }
    if (i == 0) g_rowptr[NN] = NEDGE;
}

__global__ __launch_bounds__(256) void fill_kernel(
    const int* __restrict__ er, const int* __restrict__ ec,
    const float* __restrict__ ev)
{
    int e = blockIdx.x * 256 + threadIdx.x;
    if (e >= NEDGE) return;
    int row = er[e];
    int pos = atomicAdd(&g_cursor[row], 1);
    g_ecv[pos] = make_int2(ec[e], __float_as_int(ev[e]));
}

// ---------------------------------------------------------------------------
// Fused layer kernel (round-6 config: 64 rows, 512 threads, 3 CTAs/SM).
// Gather now reads the bf16 mirror: ONE 4B/lane load per edge covering
// cols {2*lane, 2*lane+1}; accumulate fp32.
// ---------------------------------------------------------------------------
template<int DOUT, int LAYER>
__global__ __launch_bounds__(512, 3) void layer_fused_kernel(
    const float* __restrict__ W1, const float* __restrict__ b1,
    const float* __restrict__ W2, const float* __restrict__ b2)
{
    const float*         __restrict__ feats  = (LAYER == 0) ? g_feats0 : g_a1;
    const __nv_bfloat16* __restrict__ featsh = (LAYER == 0) ? g_f0h    : g_a1h;
    float*               out                 = (LAYER == 0) ? g_a1     : g_a2;

    extern __shared__ float sm[];
    float* Xs  = sm;                    // [64][65], k-major: Xs[k*65 + node]
    float* Ys  = Xs + 64 * 65;          // [64][65]
    float* W1s = Ys + 64 * 65;          // [64*DOUT]
    float* W2s = W1s + 64 * DOUT;       // [64*DOUT]
    float* Bs  = W2s + 64 * DOUT;       // [DOUT]

    const int tid  = threadIdx.x;
    const int r0   = blockIdx.x * 64;
    const int warp = tid >> 5;
    const int lane = tid & 31;

    // ---- stage W (float4) and bias sum ----
    for (int idx = tid; idx < 64 * DOUT / 4; idx += 512) {
        ((float4*)W1s)[idx] = ((const float4*)W1)[idx];
        ((float4*)W2s)[idx] = ((const float4*)W2)[idx];
    }
    if (tid < DOUT) Bs[tid] = b1[tid] + b2[tid];

    // ---- pull-mode gather: ONE bf162 load per edge, fp32 accumulate ----
    const __nv_bfloat162* __restrict__ fh2 = (const __nv_bfloat162*)featsh;
    #pragma unroll 1
    for (int i = 0; i < 4; i++) {
        int rl = warp * 4 + i;
        int gr = r0 + rl;
        float f0 = 0.f, f1 = 0.f, h0 = 0.f, h1 = 0.f;
        if (gr < NN) {
            f0 = feats[gr * 64 + 2 * lane];
            f1 = feats[gr * 64 + 2 * lane + 1];
            int beg = g_rowptr[gr];
            int end = g_rowptr[gr + 1];
            #pragma unroll 4
            for (int e = beg; e < end; e++) {
                int2 cv = g_ecv[e];                 // same addr warp-wide
                float v = __int_as_float(cv.y);
                float2 g = __bfloat1622float2(fh2[(size_t)cv.x * 32 + lane]);
                h0 += g.x * v;
                h1 += g.y * v;
            }
        }
        Xs[(2 * lane + 0) * 65 + rl] = f0 + h0;
        Xs[(2 * lane + 1) * 65 + rl] = f1 + h1;
        Ys[(2 * lane + 0) * 65 + rl] = f0 * h0;
        Ys[(2 * lane + 1) * 65 + rl] = f1 * h1;
    }
    __syncthreads();

    // ---- dense GEMM: thread (tx,ty) -> 2 nodes x JT outputs ----
    constexpr int JT = DOUT / 16;       // 4 (layer0) or 2 (layer1)
    const int tx = tid & 15;
    const int ty = tid >> 4;            // 0..31

    float acc[2][JT];
    #pragma unroll
    for (int i = 0; i < 2; i++)
        #pragma unroll
        for (int j = 0; j < JT; j++)
            acc[i][j] = Bs[tx * JT + j];

    for (int k = 0; k < 64; k++) {
        float x[2], y[2];
        #pragma unroll
        for (int i = 0; i < 2; i++) {
            x[i] = Xs[k * 65 + ty * 2 + i];
            y[i] = Ys[k * 65 + ty * 2 + i];
        }
        float w1[JT], w2[JT];
        if constexpr (JT == 4) {
            float4 a = *(const float4*)&W1s[k * DOUT + tx * 4];
            float4 b = *(const float4*)&W2s[k * DOUT + tx * 4];
            w1[0] = a.x; w1[1] = a.y; w1[2] = a.z; w1[3] = a.w;
            w2[0] = b.x; w2[1] = b.y; w2[2] = b.z; w2[3] = b.w;
        } else {
            float2 a = *(const float2*)&W1s[k * DOUT + tx * 2];
            float2 b = *(const float2*)&W2s[k * DOUT + tx * 2];
            w1[0] = a.x; w1[1] = a.y;
            w2[0] = b.x; w2[1] = b.y;
        }
        #pragma unroll
        for (int i = 0; i < 2; i++)
            #pragma unroll
            for (int j = 0; j < JT; j++)
                acc[i][j] += x[i] * w1[j] + y[i] * w2[j];
    }

    // ---- epilogue: leaky_relu + L2 normalize (+ bf16 mirror for layer0) ----
    #pragma unroll
    for (int i = 0; i < 2; i++) {
        float p = 0.f;
        #pragma unroll
        for (int j = 0; j < JT; j++) {
            float v = acc[i][j];
            v = (v > 0.f) ? v : 0.01f * v;
            acc[i][j] = v;
            p += v * v;
        }
        p += __shfl_xor_sync(0xFFFFFFFFu, p, 1, 16);
        p += __shfl_xor_sync(0xFFFFFFFFu, p, 2, 16);
        p += __shfl_xor_sync(0xFFFFFFFFu, p, 4, 16);
        p += __shfl_xor_sync(0xFFFFFFFFu, p, 8, 16);
        float inv = 1.f / fmaxf(sqrtf(p), 1e-12f);
        int gr = r0 + ty * 2 + i;
        if (gr < NN) {
            if constexpr (JT == 4) {
                float4 o = make_float4(acc[i][0] * inv, acc[i][1] * inv,
                                       acc[i][2] * inv, acc[i][3] * inv);
                ((float4*)out)[gr * 16 + tx] = o;
                // bf16 mirror for layer1's gather
                __nv_bfloat162 lo = __float22bfloat162_rn(make_float2(o.x, o.y));
                __nv_bfloat162 hi = __float22bfloat162_rn(make_float2(o.z, o.w));
                ((__nv_bfloat162*)g_a1h)[(gr * 16 + tx) * 2 + 0] = lo;
                ((__nv_bfloat162*)g_a1h)[(gr * 16 + tx) * 2 + 1] = hi;
            } else {
                float2 o = make_float2(acc[i][0] * inv, acc[i][1] * inv);
                ((float2*)out)[gr * (DOUT / 2) + tx] = o;
            }
        }
    }
}

// ---------------------------------------------------------------------------
// Scoring — warp per pair, dot over concat(a0[64], a1[64], a2[32]).
// ---------------------------------------------------------------------------
__global__ __launch_bounds__(256) void score_kernel(
    const int* __restrict__ uids, const int* __restrict__ iids,
    float* __restrict__ out)
{
    int w = (blockIdx.x * 256 + threadIdx.x) >> 5;
    int l = threadIdx.x & 31;
    if (w >= NB) return;
    int u  = uids[w];
    int it = NU + iids[w];

    const float* fu = g_feats0 + u  * 64;
    const float* fi = g_feats0 + it * 64;
    float s = fu[l] * fi[l] + fu[l + 32] * fi[l + 32];
    const float* au = g_a1 + u  * 64;
    const float* ai = g_a1 + it * 64;
    s += au[l] * ai[l] + au[l + 32] * ai[l + 32];
    s += g_a2[u * 32 + l] * g_a2[it * 32 + l];

    s += __shfl_xor_sync(0xFFFFFFFFu, s, 16);
    s += __shfl_xor_sync(0xFFFFFFFFu, s, 8);
    s += __shfl_xor_sync(0xFFFFFFFFu, s, 4);
    s += __shfl_xor_sync(0xFFFFFFFFu, s, 2);
    s += __shfl_xor_sync(0xFFFFFFFFu, s, 1);
    if (l == 0) out[w] = s;
}

// ---------------------------------------------------------------------------
extern "C" void kernel_launch(void* const* d_in, const int* in_sizes, int n_in,
                              void* d_out, int out_size)
{
    const int*   er   = (const int*)  d_in[0];
    const int*   ec   = (const int*)  d_in[1];
    const float* ev   = (const float*)d_in[2];
    const float* ue   = (const float*)d_in[3];
    const float* ee   = (const float*)d_in[4];
    const float* W1_0 = (const float*)d_in[5];
    const float* b1_0 = (const float*)d_in[6];
    const float* W2_0 = (const float*)d_in[7];
    const float* b2_0 = (const float*)d_in[8];
    const float* W1_1 = (const float*)d_in[9];
    const float* b1_1 = (const float*)d_in[10];
    const float* W2_1 = (const float*)d_in[11];
    const float* b2_1 = (const float*)d_in[12];
    const int*   uids = (const int*)  d_in[13];
    const int*   iids = (const int*)  d_in[14];
    float*       out  = (float*)d_out;

    const size_t smem64 = (size_t)(64 * 65 * 2 + 64 * 64 * 2 + 64) * sizeof(float);
    const size_t smem32 = (size_t)(64 * 65 * 2 + 64 * 32 * 2 + 32) * sizeof(float);
    cudaFuncSetAttribute(layer_fused_kernel<64, 0>,
                         cudaFuncAttributeMaxDynamicSharedMemorySize, (int)smem64);
    cudaFuncSetAttribute(layer_fused_kernel<32, 1>,
                         cudaFuncAttributeMaxDynamicSharedMemorySize, (int)smem32);

    const int layer_blocks = (NN + 63) / 64;
    const int eblocks = (NEDGE + 255) / 256;
    const int nblocks = (NN + 255) / 256;

    concat_kernel<<<(NN * 16 + 255) / 256, 256>>>(ue, ee);
    // CSR build
    zero_cnt_kernel<<<nblocks, 256>>>();
    hist_kernel<<<eblocks, 256>>>(er);
    scan1_kernel<<<NBLK_SCAN, SCAN_ELEMS>>>();
    scan2_kernel<<<1, 256>>>();
    scan3_kernel<<<nblocks, 256>>>();
    fill_kernel<<<eblocks, 256>>>(er, ec, ev);
    // Fused layers
    layer_fused_kernel<64, 0><<<layer_blocks, 512, smem64>>>(W1_0, b1_0, W2_0, b2_0);
    layer_fused_kernel<32, 1><<<layer_blocks, 512, smem32>>>(W1_1, b1_1, W2_1, b2_1);
    score_kernel<<<(NB * 32) / 256, 256>>>(uids, iids, out);
}

// round 12
// speedup vs baseline: 1.0013x; 1.0013x over previous
#include <cuda_runtime.h>

// Problem constants (match reference_code)
#define NU    30000
#define NENT  70000
#define NN    100000          // NU + NENT
#define NEDGE 1600000
#define NB    4096

#define SCAN_ELEMS 512
#define NBLK_SCAN  ((NN + SCAN_ELEMS - 1) / SCAN_ELEMS)   // 196

// Scratch (device globals: allocation-free rule).
__device__ float g_feats0[NN * 64];
__device__ float g_a1[NN * 64];
__device__ float g_a2[NN * 32];
// CSR scratch
__device__ int   g_cnt[NN];
__device__ int   g_rowptr[NN + 1];
__device__ int   g_cursor[NN];
__device__ int   g_bsum[256];
__device__ int   g_boff[256];
__device__ int2  g_ecv[NEDGE];       // x = col, y = float bits of val

// ---------------------------------------------------------------------------
// K0: a0 = concat(user_embed, entity_embed)  (pure copy, float4)
// ---------------------------------------------------------------------------
__global__ __launch_bounds__(256) void concat_kernel(
    const float* __restrict__ ue, const float* __restrict__ ee)
{
    int idx = blockIdx.x * 256 + threadIdx.x;           // over NN*16 float4
    if (idx >= NN * 16) return;
    float4 v = (idx < NU * 16) ? ((const float4*)ue)[idx]
                               : ((const float4*)ee)[idx - NU * 16];
    ((float4*)g_feats0)[idx] = v;
}

// ---------------------------------------------------------------------------
// CSR build: zero counts -> histogram -> 3-phase exclusive scan -> fill
// ---------------------------------------------------------------------------
__global__ __launch_bounds__(256) void zero_cnt_kernel()
{
    int i = blockIdx.x * 256 + threadIdx.x;
    if (i < NN) g_cnt[i] = 0;
}

__global__ __launch_bounds__(256) void hist_kernel(const int* __restrict__ er)
{
    int e = blockIdx.x * 256 + threadIdx.x;
    if (e < NEDGE) atomicAdd(&g_cnt[er[e]], 1);
}

__global__ __launch_bounds__(SCAN_ELEMS) void scan1_kernel()
{
    __shared__ int s[SCAN_ELEMS];
    int i = blockIdx.x * SCAN_ELEMS + threadIdx.x;
    int v = (i < NN) ? g_cnt[i] : 0;
    s[threadIdx.x] = v;
    __syncthreads();
    #pragma unroll
    for (int off = 1; off < SCAN_ELEMS; off <<= 1) {
        int t = (threadIdx.x >= off) ? s[threadIdx.x - off] : 0;
        __syncthreads();
        s[threadIdx.x] += t;
        __syncthreads();
    }
    if (i < NN) g_rowptr[i] = s[threadIdx.x] - v;        // exclusive within block
    if (threadIdx.x == SCAN_ELEMS - 1) g_bsum[blockIdx.x] = s[SCAN_ELEMS - 1];
}

__global__ __launch_bounds__(256) void scan2_kernel()
{
    __shared__ int s[256];
    int v = (threadIdx.x < NBLK_SCAN) ? g_bsum[threadIdx.x] : 0;
    s[threadIdx.x] = v;
    __syncthreads();
    #pragma unroll
    for (int off = 1; off < 256; off <<= 1) {
        int t = (threadIdx.x >= off) ? s[threadIdx.x - off] : 0;
        __syncthreads();
        s[threadIdx.x] += t;
        __syncthreads();
    }
    g_boff[threadIdx.x] = s[threadIdx.x] - v;            // exclusive
}

__global__ __launch_bounds__(256) void scan3_kernel()
{
    int i = blockIdx.x * 256 + threadIdx.x;
    if (i < NN) {
        int rp = g_rowptr[i] + g_boff[i / SCAN_ELEMS];
        g_rowptr[i] = rp;
        g_cursor[i] = rp;
    }
    if (i == 0) g_rowptr[NN] = NEDGE;
}

__global__ __launch_bounds__(256) void fill_kernel(
    const int* __restrict__ er, const int* __restrict__ ec,
    const float* __restrict__ ev)
{
    int e = blockIdx.x * 256 + threadIdx.x;
    if (e >= NEDGE) return;
    int row = er[e];
    int pos = atomicAdd(&g_cursor[row], 1);
    g_ecv[pos] = make_int2(ec[e], __float_as_int(ev[e]));
}

// ---------------------------------------------------------------------------
// Fused layer kernel: pull-mode SpMM gather directly into shared Xs/Ys,
// then dense GEMM + leaky_relu + L2 normalize.
// Block = 64 rows, 512 threads (16 warps, warp handles 4 rows), 3 CTAs/SM.
// Lane covers feature cols {lane, lane+32} -> two 128B-line LDG.32 per edge.
// Edge loop unrolled 8 deep -> up to 16 independent feature LDGs in flight.
// ---------------------------------------------------------------------------
template<int DOUT, int LAYER>
__global__ __launch_bounds__(512, 3) void layer_fused_kernel(
    const float* __restrict__ W1, const float* __restrict__ b1,
    const float* __restrict__ W2, const float* __restrict__ b2)
{
    const float* __restrict__ feats = (LAYER == 0) ? g_feats0 : g_a1;
    float*       out                = (LAYER == 0) ? g_a1     : g_a2;

    extern __shared__ float sm[];
    float* Xs  = sm;                    // [64][65], k-major: Xs[k*65 + node]
    float* Ys  = Xs + 64 * 65;          // [64][65]
    float* W1s = Ys + 64 * 65;          // [64*DOUT]
    float* W2s = W1s + 64 * DOUT;       // [64*DOUT]
    float* Bs  = W2s + 64 * DOUT;       // [DOUT]

    const int tid  = threadIdx.x;
    const int r0   = blockIdx.x * 64;
    const int warp = tid >> 5;
    const int lane = tid & 31;

    // ---- stage W (float4) and bias sum ----
    for (int idx = tid; idx < 64 * DOUT / 4; idx += 512) {
        ((float4*)W1s)[idx] = ((const float4*)W1)[idx];
        ((float4*)W2s)[idx] = ((const float4*)W2)[idx];
    }
    if (tid < DOUT) Bs[tid] = b1[tid] + b2[tid];

    // ---- pull-mode gather: h_neigh accumulated in registers ----
    #pragma unroll 1
    for (int i = 0; i < 4; i++) {
        int rl = warp * 4 + i;
        int gr = r0 + rl;
        float f0 = 0.f, f1 = 0.f, h0 = 0.f, h1 = 0.f;
        if (gr < NN) {
            f0 = feats[gr * 64 + lane];
            f1 = feats[gr * 64 + 32 + lane];
            int beg = g_rowptr[gr];
            int end = g_rowptr[gr + 1];
            #pragma unroll 8
            for (int e = beg; e < end; e++) {
                int2 cv = g_ecv[e];                 // same addr warp-wide
                float v = __int_as_float(cv.y);
                const float* fp = feats + (size_t)cv.x * 64;
                h0 += fp[lane] * v;
                h1 += fp[32 + lane] * v;
            }
        }
        Xs[lane * 65 + rl]        = f0 + h0;
        Xs[(lane + 32) * 65 + rl] = f1 + h1;
        Ys[lane * 65 + rl]        = f0 * h0;
        Ys[(lane + 32) * 65 + rl] = f1 * h1;
    }
    __syncthreads();

    // ---- dense GEMM: thread (tx,ty) -> 2 nodes x JT outputs ----
    constexpr int JT = DOUT / 16;       // 4 (layer0) or 2 (layer1)
    const int tx = tid & 15;
    const int ty = tid >> 4;            // 0..31

    float acc[2][JT];
    #pragma unroll
    for (int i = 0; i < 2; i++)
        #pragma unroll
        for (int j = 0; j < JT; j++)
            acc[i][j] = Bs[tx * JT + j];

    for (int k = 0; k < 64; k++) {
        float x[2], y[2];
        #pragma unroll
        for (int i = 0; i < 2; i++) {
            x[i] = Xs[k * 65 + ty * 2 + i];
            y[i] = Ys[k * 65 + ty * 2 + i];
        }
        float w1[JT], w2[JT];
        if constexpr (JT == 4) {
            float4 a = *(const float4*)&W1s[k * DOUT + tx * 4];
            float4 b = *(const float4*)&W2s[k * DOUT + tx * 4];
            w1[0] = a.x; w1[1] = a.y; w1[2] = a.z; w1[3] = a.w;
            w2[0] = b.x; w2[1] = b.y; w2[2] = b.z; w2[3] = b.w;
        } else {
            float2 a = *(const float2*)&W1s[k * DOUT + tx * 2];
            float2 b = *(const float2*)&W2s[k * DOUT + tx * 2];
            w1[0] = a.x; w1[1] = a.y;
            w2[0] = b.x; w2[1] = b.y;
        }
        #pragma unroll
        for (int i = 0; i < 2; i++)
            #pragma unroll
            for (int j = 0; j < JT; j++)
                acc[i][j] += x[i] * w1[j] + y[i] * w2[j];
    }

    // ---- epilogue: leaky_relu + L2 normalize (width-16 shfl reduction) ----
    #pragma unroll
    for (int i = 0; i < 2; i++) {
        float p = 0.f;
        #pragma unroll
        for (int j = 0; j < JT; j++) {
            float v = acc[i][j];
            v = (v > 0.f) ? v : 0.01f * v;
            acc[i][j] = v;
            p += v * v;
        }
        p += __shfl_xor_sync(0xFFFFFFFFu, p, 1, 16);
        p += __shfl_xor_sync(0xFFFFFFFFu, p, 2, 16);
        p += __shfl_xor_sync(0xFFFFFFFFu, p, 4, 16);
        p += __shfl_xor_sync(0xFFFFFFFFu, p, 8, 16);
        float inv = 1.f / fmaxf(sqrtf(p), 1e-12f);
        int gr = r0 + ty * 2 + i;
        if (gr < NN) {
            if constexpr (JT == 4) {
                float4 o = make_float4(acc[i][0] * inv, acc[i][1] * inv,
                                       acc[i][2] * inv, acc[i][3] * inv);
                ((float4*)out)[gr * (DOUT / 4) + tx] = o;
            } else {
                float2 o = make_float2(acc[i][0] * inv, acc[i][1] * inv);
                ((float2*)out)[gr * (DOUT / 2) + tx] = o;
            }
        }
    }
}

// ---------------------------------------------------------------------------
// Scoring — warp per pair, dot over concat(a0[64], a1[64], a2[32]).
// ---------------------------------------------------------------------------
__global__ __launch_bounds__(256) void score_kernel(
    const int* __restrict__ uids, const int* __restrict__ iids,
    float* __restrict__ out)
{
    int w = (blockIdx.x * 256 + threadIdx.x) >> 5;
    int l = threadIdx.x & 31;
    if (w >= NB) return;
    int u  = uids[w];
    int it = NU + iids[w];

    const float* fu = g_feats0 + u  * 64;
    const float* fi = g_feats0 + it * 64;
    float s = fu[l] * fi[l] + fu[l + 32] * fi[l + 32];
    const float* au = g_a1 + u  * 64;
    const float* ai = g_a1 + it * 64;
    s += au[l] * ai[l] + au[l + 32] * ai[l + 32];
    s += g_a2[u * 32 + l] * g_a2[it * 32 + l];

    s += __shfl_xor_sync(0xFFFFFFFFu, s, 16);
    s += __shfl_xor_sync(0xFFFFFFFFu, s, 8);
    s += __shfl_xor_sync(0xFFFFFFFFu, s, 4);
    s += __shfl_xor_sync(0xFFFFFFFFu, s, 2);
    s += __shfl_xor_sync(0xFFFFFFFFu, s, 1);
    if (l == 0) out[w] = s;
}

// ---------------------------------------------------------------------------
extern "C" void kernel_launch(void* const* d_in, const int* in_sizes, int n_in,
                              void* d_out, int out_size)
{
    const int*   er   = (const int*)  d_in[0];
    const int*   ec   = (const int*)  d_in[1];
    const float* ev   = (const float*)d_in[2];
    const float* ue   = (const float*)d_in[3];
    const float* ee   = (const float*)d_in[4];
    const float* W1_0 = (const float*)d_in[5];
    const float* b1_0 = (const float*)d_in[6];
    const float* W2_0 = (const float*)d_in[7];
    const float* b2_0 = (const float*)d_in[8];
    const float* W1_1 = (const float*)d_in[9];
    const float* b1_1 = (const float*)d_in[10];
    const float* W2_1 = (const float*)d_in[11];
    const float* b2_1 = (const float*)d_in[12];
    const int*   uids = (const int*)  d_in[13];
    const int*   iids = (const int*)  d_in[14];
    float*       out  = (float*)d_out;

    const size_t smem64 = (size_t)(64 * 65 * 2 + 64 * 64 * 2 + 64) * sizeof(float);
    const size_t smem32 = (size_t)(64 * 65 * 2 + 64 * 32 * 2 + 32) * sizeof(float);
    cudaFuncSetAttribute(layer_fused_kernel<64, 0>,
                         cudaFuncAttributeMaxDynamicSharedMemorySize, (int)smem64);
    cudaFuncSetAttribute(layer_fused_kernel<32, 1>,
                         cudaFuncAttributeMaxDynamicSharedMemorySize, (int)smem32);

    const int layer_blocks = (NN + 63) / 64;
    const int eblocks = (NEDGE + 255) / 256;
    const int nblocks = (NN + 255) / 256;

    concat_kernel<<<(NN * 16 + 255) / 256, 256>>>(ue, ee);
    // CSR build
    zero_cnt_kernel<<<nblocks, 256>>>();
    hist_kernel<<<eblocks, 256>>>(er);
    scan1_kernel<<<NBLK_SCAN, SCAN_ELEMS>>>();
    scan2_kernel<<<1, 256>>>();
    scan3_kernel<<<nblocks, 256>>>();
    fill_kernel<<<eblocks, 256>>>(er, ec, ev);
    // Fused layers
    layer_fused_kernel<64, 0><<<layer_blocks, 512, smem64>>>(W1_0, b1_0, W2_0, b2_0);
    layer_fused_kernel<32, 1><<<layer_blocks, 512, smem32>>>(W1_1, b1_1, W2_1, b2_1);
    score_kernel<<<(NB * 32) / 256, 256>>>(uids, iids, out);
}

// round 13
// speedup vs baseline: 1.5182x; 1.5162x over previous
#include <cuda_runtime.h>

// Problem constants (match reference_code)
#define NU    30000
#define NENT  70000
#define NN    100000          // NU + NENT
#define NEDGE 1600000
#define NB    4096

#define SCAN_ELEMS 512
#define NBLK_SCAN  ((NN + SCAN_ELEMS - 1) / SCAN_ELEMS)   // 196

// Scratch (device globals: allocation-free rule).
__device__ float g_feats0[NN * 64];
__device__ float g_a1[NN * 64];
__device__ float g_a2[NN * 32];
// CSR scratch
__device__ int   g_cnt[NN];
__device__ int   g_rowptr[NN + 1];
__device__ int   g_cursor[NN];
__device__ int   g_bsum[256];
__device__ int   g_boff[256];
__device__ int2  g_ecv[NEDGE];       // x = col, y = float bits of val

// ---------------------------------------------------------------------------
// K0: a0 = concat(user_embed, entity_embed) (float4 copy) + zero CSR counters
// ---------------------------------------------------------------------------
__global__ __launch_bounds__(256) void concat_kernel(
    const float* __restrict__ ue, const float* __restrict__ ee)
{
    int idx = blockIdx.x * 256 + threadIdx.x;           // over NN*16 float4
    if (idx < NN) g_cnt[idx] = 0;
    if (idx >= NN * 16) return;
    float4 v = (idx < NU * 16) ? ((const float4*)ue)[idx]
                               : ((const float4*)ee)[idx - NU * 16];
    ((float4*)g_feats0)[idx] = v;
}

// ---------------------------------------------------------------------------
// CSR build: histogram -> 3-phase exclusive scan -> fill
// ---------------------------------------------------------------------------
__global__ __launch_bounds__(256) void hist_kernel(const int* __restrict__ er)
{
    int e = blockIdx.x * 256 + threadIdx.x;
    if (e < NEDGE) atomicAdd(&g_cnt[er[e]], 1);
}

__global__ __launch_bounds__(SCAN_ELEMS) void scan1_kernel()
{
    __shared__ int s[SCAN_ELEMS];
    int i = blockIdx.x * SCAN_ELEMS + threadIdx.x;
    int v = (i < NN) ? g_cnt[i] : 0;
    s[threadIdx.x] = v;
    __syncthreads();
    #pragma unroll
    for (int off = 1; off < SCAN_ELEMS; off <<= 1) {
        int t = (threadIdx.x >= off) ? s[threadIdx.x - off] : 0;
        __syncthreads();
        s[threadIdx.x] += t;
        __syncthreads();
    }
    if (i < NN) g_rowptr[i] = s[threadIdx.x] - v;        // exclusive within block
    if (threadIdx.x == SCAN_ELEMS - 1) g_bsum[blockIdx.x] = s[SCAN_ELEMS - 1];
}

__global__ __launch_bounds__(256) void scan2_kernel()
{
    __shared__ int s[256];
    int v = (threadIdx.x < NBLK_SCAN) ? g_bsum[threadIdx.x] : 0;
    s[threadIdx.x] = v;
    __syncthreads();
    #pragma unroll
    for (int off = 1; off < 256; off <<= 1) {
        int t = (threadIdx.x >= off) ? s[threadIdx.x - off] : 0;
        __syncthreads();
        s[threadIdx.x] += t;
        __syncthreads();
    }
    g_boff[threadIdx.x] = s[threadIdx.x] - v;            // exclusive
}

__global__ __launch_bounds__(256) void scan3_kernel()
{
    int i = blockIdx.x * 256 + threadIdx.x;
    if (i < NN) {
        int rp = g_rowptr[i] + g_boff[i / SCAN_ELEMS];
        g_rowptr[i] = rp;
        g_cursor[i] = rp;
    }
    if (i == 0) g_rowptr[NN] = NEDGE;
}

__global__ __launch_bounds__(256) void fill_kernel(
    const int* __restrict__ er, const int* __restrict__ ec,
    const float* __restrict__ ev)
{
    int e = blockIdx.x * 256 + threadIdx.x;
    if (e >= NEDGE) return;
    int row = er[e];
    int pos = atomicAdd(&g_cursor[row], 1);
    g_ecv[pos] = make_int2(ec[e], __float_as_int(ev[e]));
}

// ---------------------------------------------------------------------------
// Fused layer kernel (round-6 exact): pull-mode SpMM gather into shared
// Xs/Ys, then dense GEMM + leaky_relu + L2 normalize.
// Block = 64 rows, 512 threads (16 warps, warp handles 4 rows), 3 CTAs/SM.
// Lane covers feature cols {lane, lane+32} -> two 128B-line LDG.32 per edge.
// Edge loop unroll 4 (validated optimum).
// ---------------------------------------------------------------------------
template<int DOUT, int LAYER>
__global__ __launch_bounds__(512, 3) void layer_fused_kernel(
    const float* __restrict__ W1, const float* __restrict__ b1,
    const float* __restrict__ W2, const float* __restrict__ b2)
{
    const float* __restrict__ feats = (LAYER == 0) ? g_feats0 : g_a1;
    float*       out                = (LAYER == 0) ? g_a1     : g_a2;

    extern __shared__ float sm[];
    float* Xs  = sm;                    // [64][65], k-major: Xs[k*65 + node]
    float* Ys  = Xs + 64 * 65;          // [64][65]
    float* W1s = Ys + 64 * 65;          // [64*DOUT]
    float* W2s = W1s + 64 * DOUT;       // [64*DOUT]
    float* Bs  = W2s + 64 * DOUT;       // [DOUT]

    const int tid  = threadIdx.x;
    const int r0   = blockIdx.x * 64;
    const int warp = tid >> 5;
    const int lane = tid & 31;

    // ---- stage W (float4) and bias sum ----
    for (int idx = tid; idx < 64 * DOUT / 4; idx += 512) {
        ((float4*)W1s)[idx] = ((const float4*)W1)[idx];
        ((float4*)W2s)[idx] = ((const float4*)W2)[idx];
    }
    if (tid < DOUT) Bs[tid] = b1[tid] + b2[tid];

    // ---- pull-mode gather: h_neigh accumulated in registers ----
    #pragma unroll 1
    for (int i = 0; i < 4; i++) {
        int rl = warp * 4 + i;
        int gr = r0 + rl;
        float f0 = 0.f, f1 = 0.f, h0 = 0.f, h1 = 0.f;
        if (gr < NN) {
            f0 = feats[gr * 64 + lane];
            f1 = feats[gr * 64 + 32 + lane];
            int beg = g_rowptr[gr];
            int end = g_rowptr[gr + 1];
            #pragma unroll 4
            for (int e = beg; e < end; e++) {
                int2 cv = g_ecv[e];                 // same addr warp-wide
                float v = __int_as_float(cv.y);
                const float* fp = feats + (size_t)cv.x * 64;
                h0 += fp[lane] * v;
                h1 += fp[32 + lane] * v;
            }
        }
        Xs[lane * 65 + rl]        = f0 + h0;
        Xs[(lane + 32) * 65 + rl] = f1 + h1;
        Ys[lane * 65 + rl]        = f0 * h0;
        Ys[(lane + 32) * 65 + rl] = f1 * h1;
    }
    __syncthreads();

    // ---- dense GEMM: thread (tx,ty) -> 2 nodes x JT outputs ----
    constexpr int JT = DOUT / 16;       // 4 (layer0) or 2 (layer1)
    const int tx = tid & 15;
    const int ty = tid >> 4;            // 0..31

    float acc[2][JT];
    #pragma unroll
    for (int i = 0; i < 2; i++)
        #pragma unroll
        for (int j = 0; j < JT; j++)
            acc[i][j] = Bs[tx * JT + j];

    for (int k = 0; k < 64; k++) {
        float x[2], y[2];
        #pragma unroll
        for (int i = 0; i < 2; i++) {
            x[i] = Xs[k * 65 + ty * 2 + i];
            y[i] = Ys[k * 65 + ty * 2 + i];
        }
        float w1[JT], w2[JT];
        if constexpr (JT == 4) {
            float4 a = *(const float4*)&W1s[k * DOUT + tx * 4];
            float4 b = *(const float4*)&W2s[k * DOUT + tx * 4];
            w1[0] = a.x; w1[1] = a.y; w1[2] = a.z; w1[3] = a.w;
            w2[0] = b.x; w2[1] = b.y; w2[2] = b.z; w2[3] = b.w;
        } else {
            float2 a = *(const float2*)&W1s[k * DOUT + tx * 2];
            float2 b = *(const float2*)&W2s[k * DOUT + tx * 2];
            w1[0] = a.x; w1[1] = a.y;
            w2[0] = b.x; w2[1] = b.y;
        }
        #pragma unroll
        for (int i = 0; i < 2; i++)
            #pragma unroll
            for (int j = 0; j < JT; j++)
                acc[i][j] += x[i] * w1[j] + y[i] * w2[j];
    }

    // ---- epilogue: leaky_relu + L2 normalize (width-16 shfl reduction) ----
    #pragma unroll
    for (int i = 0; i < 2; i++) {
        float p = 0.f;
        #pragma unroll
        for (int j = 0; j < JT; j++) {
            float v = acc[i][j];
            v = (v > 0.f) ? v : 0.01f * v;
            acc[i][j] = v;
            p += v * v;
        }
        p += __shfl_xor_sync(0xFFFFFFFFu, p, 1, 16);
        p += __shfl_xor_sync(0xFFFFFFFFu, p, 2, 16);
        p += __shfl_xor_sync(0xFFFFFFFFu, p, 4, 16);
        p += __shfl_xor_sync(0xFFFFFFFFu, p, 8, 16);
        float inv = 1.f / fmaxf(sqrtf(p), 1e-12f);
        int gr = r0 + ty * 2 + i;
        if (gr < NN) {
            if constexpr (JT == 4) {
                float4 o = make_float4(acc[i][0] * inv, acc[i][1] * inv,
                                       acc[i][2] * inv, acc[i][3] * inv);
                ((float4*)out)[gr * (DOUT / 4) + tx] = o;
            } else {
                float2 o = make_float2(acc[i][0] * inv, acc[i][1] * inv);
                ((float2*)out)[gr * (DOUT / 2) + tx] = o;
            }
        }
    }
}

// ---------------------------------------------------------------------------
// Scoring — warp per pair, dot over concat(a0[64], a1[64], a2[32]).
// ---------------------------------------------------------------------------
__global__ __launch_bounds__(256) void score_kernel(
    const int* __restrict__ uids, const int* __restrict__ iids,
    float* __restrict__ out)
{
    int w = (blockIdx.x * 256 + threadIdx.x) >> 5;
    int l = threadIdx.x & 31;
    if (w >= NB) return;
    int u  = uids[w];
    int it = NU + iids[w];

    const float* fu = g_feats0 + u  * 64;
    const float* fi = g_feats0 + it * 64;
    float s = fu[l] * fi[l] + fu[l + 32] * fi[l + 32];
    const float* au = g_a1 + u  * 64;
    const float* ai = g_a1 + it * 64;
    s += au[l] * ai[l] + au[l + 32] * ai[l + 32];
    s += g_a2[u * 32 + l] * g_a2[it * 32 + l];

    s += __shfl_xor_sync(0xFFFFFFFFu, s, 16);
    s += __shfl_xor_sync(0xFFFFFFFFu, s, 8);
    s += __shfl_xor_sync(0xFFFFFFFFu, s, 4);
    s += __shfl_xor_sync(0xFFFFFFFFu, s, 2);
    s += __shfl_xor_sync(0xFFFFFFFFu, s, 1);
    if (l == 0) out[w] = s;
}

// ---------------------------------------------------------------------------
extern "C" void kernel_launch(void* const* d_in, const int* in_sizes, int n_in,
                              void* d_out, int out_size)
{
    const int*   er   = (const int*)  d_in[0];
    const int*   ec   = (const int*)  d_in[1];
    const float* ev   = (const float*)d_in[2];
    const float* ue   = (const float*)d_in[3];
    const float* ee   = (const float*)d_in[4];
    const float* W1_0 = (const float*)d_in[5];
    const float* b1_0 = (const float*)d_in[6];
    const float* W2_0 = (const float*)d_in[7];
    const float* b2_0 = (const float*)d_in[8];
    const float* W1_1 = (const float*)d_in[9];
    const float* b1_1 = (const float*)d_in[10];
    const float* W2_1 = (const float*)d_in[11];
    const float* b2_1 = (const float*)d_in[12];
    const int*   uids = (const int*)  d_in[13];
    const int*   iids = (const int*)  d_in[14];
    float*       out  = (float*)d_out;

    const size_t smem64 = (size_t)(64 * 65 * 2 + 64 * 64 * 2 + 64) * sizeof(float);
    const size_t smem32 = (size_t)(64 * 65 * 2 + 64 * 32 * 2 + 32) * sizeof(float);
    cudaFuncSetAttribute(layer_fused_kernel<64, 0>,
                         cudaFuncAttributeMaxDynamicSharedMemorySize, (int)smem64);
    cudaFuncSetAttribute(layer_fused_kernel<32, 1>,
                         cudaFuncAttributeMaxDynamicSharedMemorySize, (int)smem32);

    const int layer_blocks = (NN + 63) / 64;
    const int eblocks = (NEDGE + 255) / 256;

    concat_kernel<<<(NN * 16 + 255) / 256, 256>>>(ue, ee);   // also zeros g_cnt
    // CSR build
    hist_kernel<<<eblocks, 256>>>(er);
    scan1_kernel<<<NBLK_SCAN, SCAN_ELEMS>>>();
    scan2_kernel<<<1, 256>>>();
    scan3_kernel<<<(NN + 255) / 256, 256>>>();
    fill_kernel<<<eblocks, 256>>>(er, ec, ev);
    // Fused layers
    layer_fused_kernel<64, 0><<<layer_blocks, 512, smem64>>>(W1_0, b1_0, W2_0, b2_0);
    layer_fused_kernel<32, 1><<<layer_blocks, 512, smem32>>>(W1_1, b1_1, W2_1, b2_1);
    score_kernel<<<(NB * 32) / 256, 256>>>(uids, iids, out);
}